// round 6
// baseline (speedup 1.0000x reference)
#include <cuda_runtime.h>
#include <cfloat>
#include <math.h>

// embed (8,4096,768) f32, centers (2048,768) f32 -> argmin_c ||x-c|| as f32 (8*4096)
// Phase 1: fp32 tiled GEMM ranks clusters by (c^2 - 2 x.c), keeps top-2 per token.
// Phase 2: fp64 recompute of both candidates, then bit-replay of the reference's
//          fp32 pipeline: round x2,c2,cross to f32; s = fl(fl(x2+c2)-fl(2*cr));
//          d = f32 sqrt(max(s,0)); pick smaller d, lower index on ties.

#define D_FIXED 768
#define TM 64
#define TN 128
#define BK 16
#define NTHREADS 256
#define C_FIXED 2048
#define N_FIXED 32768

__device__ float  g_csq[C_FIXED];
__device__ double g_csqd[C_FIXED];
__device__ int    g_top1[N_FIXED];
__device__ int    g_top2[N_FIXED];

// one warp per cluster: ||c||^2 in fp64 (store f64 + f32)
__global__ void csq_kernel(const float* __restrict__ centers, int C, int D) {
    int warp = (blockIdx.x * blockDim.x + threadIdx.x) >> 5;
    int lane = threadIdx.x & 31;
    if (warp >= C) return;
    const float* row = centers + (size_t)warp * D;
    double s = 0.0;
    for (int k = lane; k < D; k += 32) {
        double v = (double)row[k];
        s = fma(v, v, s);
    }
    #pragma unroll
    for (int o = 16; o > 0; o >>= 1)
        s += __shfl_down_sync(0xffffffffu, s, o);
    if (lane == 0) { g_csqd[warp] = s; g_csq[warp] = (float)s; }
}

__device__ __forceinline__ bool lt(float v, int i, float w, int j) {
    return v < w || (v == w && i < j);
}

__global__ __launch_bounds__(NTHREADS)
void rank_kernel(const float* __restrict__ X,
                 const float* __restrict__ Cent,
                 int N, int C, int D) {
    __shared__ float As[BK][TM + 4];
    __shared__ float Bs[BK][TN + 4];
    __shared__ float csq_sh[C_FIXED];

    const int t  = threadIdx.x;
    const int tx = t & 15;
    const int ty = t >> 4;
    const int row0 = blockIdx.x * TM;

    const int lm = t >> 2;
    const int lk = (t & 3) * 4;

    for (int i = t; i < C_FIXED; i += NTHREADS) csq_sh[i] = g_csq[i];
    __syncthreads();

    float b1v[4], b2v[4];
    int   b1i[4], b2i[4];
    #pragma unroll
    for (int i = 0; i < 4; i++) {
        b1v[i] = FLT_MAX; b2v[i] = FLT_MAX;
        b1i[i] = 0x7fffffff; b2i[i] = 0x7fffffff;
    }

    for (int ct = 0; ct < C; ct += TN) {
        float acc[4][8];
        #pragma unroll
        for (int i = 0; i < 4; i++)
            #pragma unroll
            for (int j = 0; j < 8; j++)
                acc[i][j] = 0.f;

        for (int kt = 0; kt < D; kt += BK) {
            {
                const float4 v = *reinterpret_cast<const float4*>(
                    X + (size_t)(row0 + lm) * D + kt + lk);
                As[lk + 0][lm] = v.x;
                As[lk + 1][lm] = v.y;
                As[lk + 2][lm] = v.z;
                As[lk + 3][lm] = v.w;
            }
            {
                const float4 v0 = *reinterpret_cast<const float4*>(
                    Cent + (size_t)(ct + lm) * D + kt + lk);
                Bs[lk + 0][lm] = v0.x;
                Bs[lk + 1][lm] = v0.y;
                Bs[lk + 2][lm] = v0.z;
                Bs[lk + 3][lm] = v0.w;
                const float4 v1 = *reinterpret_cast<const float4*>(
                    Cent + (size_t)(ct + lm + 64) * D + kt + lk);
                Bs[lk + 0][lm + 64] = v1.x;
                Bs[lk + 1][lm + 64] = v1.y;
                Bs[lk + 2][lm + 64] = v1.z;
                Bs[lk + 3][lm + 64] = v1.w;
            }
            __syncthreads();

            #pragma unroll
            for (int k = 0; k < BK; k++) {
                float a[4], b[8];
                #pragma unroll
                for (int i = 0; i < 4; i++) a[i] = As[k][ty * 4 + i];
                #pragma unroll
                for (int j = 0; j < 8; j++) b[j] = Bs[k][tx * 8 + j];
                #pragma unroll
                for (int i = 0; i < 4; i++)
                    #pragma unroll
                    for (int j = 0; j < 8; j++)
                        acc[i][j] = fmaf(a[i], b[j], acc[i][j]);
            }
            __syncthreads();
        }

        #pragma unroll
        for (int j = 0; j < 8; j++) {
            const int cidx = ct + tx * 8 + j;
            const float cs = csq_sh[cidx];
            #pragma unroll
            for (int i = 0; i < 4; i++) {
                const float s = fmaf(-2.f, acc[i][j], cs);
                if (s < b1v[i]) {
                    b2v[i] = b1v[i]; b2i[i] = b1i[i];
                    b1v[i] = s;      b1i[i] = cidx;
                } else if (s < b2v[i]) {
                    b2v[i] = s; b2i[i] = cidx;
                }
            }
        }
    }

    #pragma unroll
    for (int i = 0; i < 4; i++) {
        #pragma unroll
        for (int o = 8; o > 0; o >>= 1) {
            const float w1v = __shfl_down_sync(0xffffffffu, b1v[i], o, 16);
            const int   w1i = __shfl_down_sync(0xffffffffu, b1i[i], o, 16);
            const float w2v = __shfl_down_sync(0xffffffffu, b2v[i], o, 16);
            const int   w2i = __shfl_down_sync(0xffffffffu, b2i[i], o, 16);
            if (lt(w1v, w1i, b1v[i], b1i[i])) {
                if (lt(b1v[i], b1i[i], w2v, w2i)) { b2v[i] = b1v[i]; b2i[i] = b1i[i]; }
                else                               { b2v[i] = w2v;    b2i[i] = w2i;    }
                b1v[i] = w1v; b1i[i] = w1i;
            } else {
                if (lt(w1v, w1i, b2v[i], b2i[i])) { b2v[i] = w1v; b2i[i] = w1i; }
            }
        }
        if (tx == 0) {
            g_top1[row0 + ty * 4 + i] = b1i[i];
            g_top2[row0 + ty * 4 + i] = b2i[i];
        }
    }
}

// one warp per token: fp64 exact pieces, then bit-replay of reference fp32 epilogue
__global__ __launch_bounds__(256)
void refine_kernel(const float* __restrict__ X,
                   const float* __restrict__ Cent,
                   float* __restrict__ out, int N, int D) {
    const int warp = (blockIdx.x * blockDim.x + threadIdx.x) >> 5;
    const int lane = threadIdx.x & 31;
    if (warp >= N) return;

    const int i1 = g_top1[warp];
    const int i2 = g_top2[warp];
    const float* x  = X + (size_t)warp * D;
    const float* cA = Cent + (size_t)i1 * D;
    const float* cB = Cent + (size_t)i2 * D;

    double x2 = 0.0, crA = 0.0, crB = 0.0;
    for (int k = lane; k < D; k += 32) {
        const double xv = (double)x[k];
        x2  = fma(xv, xv, x2);
        crA = fma(xv, (double)cA[k], crA);
        crB = fma(xv, (double)cB[k], crB);
    }
    #pragma unroll
    for (int o = 16; o > 0; o >>= 1) {
        x2  += __shfl_down_sync(0xffffffffu, x2,  o);
        crA += __shfl_down_sync(0xffffffffu, crA, o);
        crB += __shfl_down_sync(0xffffffffu, crB, o);
    }
    if (lane == 0) {
        // round every intermediate to f32, then reference's elementwise ops
        const float x2f  = (float)x2;
        const float c2A  = (float)g_csqd[i1];
        const float c2B  = (float)g_csqd[i2];
        const float crAf = (float)crA;
        const float crBf = (float)crB;

        float sA = __fsub_rn(__fadd_rn(x2f, c2A), __fmul_rn(2.0f, crAf));
        float sB = __fsub_rn(__fadd_rn(x2f, c2B), __fmul_rn(2.0f, crBf));
        sA = fmaxf(sA, 0.f);
        sB = fmaxf(sB, 0.f);
        const float dA = __fsqrt_rn(sA);
        const float dB = __fsqrt_rn(sB);

        int win;
        if (dB < dA)      win = i2;
        else if (dA < dB) win = i1;
        else              win = (i1 < i2) ? i1 : i2;
        out[warp] = (float)win;
    }
}

extern "C" void kernel_launch(void* const* d_in, const int* in_sizes, int n_in,
                              void* d_out, int out_size) {
    const float* embed   = (const float*)d_in[0];
    const float* centers = (const float*)d_in[1];
    float* out = (float*)d_out;

    const int D = D_FIXED;
    const int N = in_sizes[0] / D;   // 32768
    const int C = in_sizes[1] / D;   // 2048

    {
        const int warps_per_block = NTHREADS / 32;
        const int nblk = (C + warps_per_block - 1) / warps_per_block;
        csq_kernel<<<nblk, NTHREADS>>>(centers, C, D);
    }
    rank_kernel<<<N / TM, NTHREADS>>>(embed, centers, N, C, D);
    refine_kernel<<<(N * 32 + 255) / 256, 256>>>(embed, centers, out, N, D);
}

// round 7
// speedup vs baseline: 2.0433x; 2.0433x over previous
#include <cuda_runtime.h>
#include <cfloat>
#include <math.h>

// embed (8,4096,768) f32, centers (2048,768) f32 -> argmin_c ||x-c|| as f32 (8*4096)
// Phase 1: split-TF32 tensor-core GEMM (hi/lo, 3-pass -> fp32-accurate) ranks
//          clusters by (c^2 - 2 x.c), keeps top-2 per token.
// Phase 2: fp64 recompute of both candidates + bit-replay of reference fp32
//          epilogue (proven in round 6).

#define D_FIXED 768
#define C_FIXED 2048
#define N_FIXED 32768

#define BM 128          // tokens per block
#define CT 64           // cluster chunk
#define BK 32           // k tile
#define SA 36           // padded smem row stride (floats): conflict-free ldmatrix
#define NTHREADS 256

__device__ float  g_csq[C_FIXED];
__device__ double g_csqd[C_FIXED];
__device__ int    g_top1[N_FIXED];
__device__ int    g_top2[N_FIXED];

__device__ __forceinline__ float to_tf32(float x) {
    float r;
    asm("cvt.rna.tf32.f32 %0, %1;" : "=f"(r) : "f"(x));
    return r;
}
__device__ __forceinline__ unsigned sptr(const void* p) {
    return (unsigned)__cvta_generic_to_shared(p);
}
__device__ __forceinline__ void ldsm4(unsigned* d, unsigned addr) {
    asm volatile("ldmatrix.sync.aligned.m8n8.x4.shared.b16 {%0,%1,%2,%3}, [%4];"
                 : "=r"(d[0]), "=r"(d[1]), "=r"(d[2]), "=r"(d[3]) : "r"(addr));
}
__device__ __forceinline__ void mma_tf32(float* d, const unsigned* a,
                                         unsigned b0, unsigned b1) {
    asm volatile(
        "mma.sync.aligned.m16n8k8.row.col.f32.tf32.tf32.f32 "
        "{%0,%1,%2,%3}, {%4,%5,%6,%7}, {%8,%9}, {%0,%1,%2,%3};"
        : "+f"(d[0]), "+f"(d[1]), "+f"(d[2]), "+f"(d[3])
        : "r"(a[0]), "r"(a[1]), "r"(a[2]), "r"(a[3]), "r"(b0), "r"(b1));
}
__device__ __forceinline__ bool lt(float v, int i, float w, int j) {
    return v < w || (v == w && i < j);
}

// one warp per cluster: ||c||^2 in fp64 (store f64 + f32)
__global__ void csq_kernel(const float* __restrict__ centers, int C, int D) {
    int warp = (blockIdx.x * blockDim.x + threadIdx.x) >> 5;
    int lane = threadIdx.x & 31;
    if (warp >= C) return;
    const float* row = centers + (size_t)warp * D;
    double s = 0.0;
    for (int k = lane; k < D; k += 32) {
        double v = (double)row[k];
        s = fma(v, v, s);
    }
    #pragma unroll
    for (int o = 16; o > 0; o >>= 1)
        s += __shfl_down_sync(0xffffffffu, s, o);
    if (lane == 0) { g_csqd[warp] = s; g_csq[warp] = (float)s; }
}

__global__ __launch_bounds__(NTHREADS)
void rank_kernel(const float* __restrict__ X,
                 const float* __restrict__ Cent,
                 int N, int C, int D) {
    extern __shared__ float smf[];
    float* As_hi = smf;                       // 128*36
    float* As_lo = As_hi + BM * SA;
    float* Bs_hi = As_lo + BM * SA;           // 64*36
    float* Bs_lo = Bs_hi + CT * SA;
    float* redV  = Bs_lo + CT * SA;           // 128*16
    int*   redI  = (int*)(redV + BM * 16);    // 128*16

    const int t    = threadIdx.x;
    const int lane = t & 31;
    const int wid  = t >> 5;
    const int warp_m = wid & 3;               // 0..3 (32 tokens each)
    const int warp_n = wid >> 2;              // 0..1 (32 clusters each)
    const int row0 = blockIdx.x * BM;

    // tile loader coords
    const int tr = t >> 3;                    // 0..31
    const int tc = (t & 7) * 4;               // 0,4,...,28

    // ldmatrix byte offsets (within the smem tiles)
    const int a_row = (lane < 16) ? lane : (lane - 16);
    const int a_k   = (lane < 16) ? 0 : 4;
    unsigned aoff[2];
    #pragma unroll
    for (int mt = 0; mt < 2; mt++)
        aoff[mt] = (unsigned)(((warp_m * 32 + mt * 16 + a_row) * SA + a_k) * 4);

    const int g     = lane >> 3;
    const int b_row = (g == 0) ? lane : (g == 1) ? lane - 8
                    : (g == 2) ? lane - 8 : lane - 16;
    const int b_k   = (g & 1) * 4;
    unsigned boff[2];
    #pragma unroll
    for (int p = 0; p < 2; p++)
        boff[p] = (unsigned)(((warp_n * 32 + p * 16 + b_row) * SA + b_k) * 4);

    const unsigned ah_base = sptr(As_hi), al_base = sptr(As_lo);
    const unsigned bh_base = sptr(Bs_hi), bl_base = sptr(Bs_lo);

    float v1[4], v2[4];
    int   i1[4], i2[4];
    #pragma unroll
    for (int s = 0; s < 4; s++) {
        v1[s] = FLT_MAX; v2[s] = FLT_MAX;
        i1[s] = 0x7fffffff; i2[s] = 0x7fffffff;
    }

    for (int ct = 0; ct < C; ct += CT) {
        float acc[2][4][4];
        #pragma unroll
        for (int mt = 0; mt < 2; mt++)
            #pragma unroll
            for (int nt = 0; nt < 4; nt++)
                #pragma unroll
                for (int e = 0; e < 4; e++)
                    acc[mt][nt][e] = 0.f;

        for (int kt = 0; kt < D; kt += BK) {
            // ---- stage A (128 x 32) hi/lo
            #pragma unroll
            for (int rr = 0; rr < BM; rr += 32) {
                const float4 v = *reinterpret_cast<const float4*>(
                    X + (size_t)(row0 + tr + rr) * D + kt + tc);
                float hx = to_tf32(v.x), hy = to_tf32(v.y);
                float hz = to_tf32(v.z), hw = to_tf32(v.w);
                *reinterpret_cast<float4*>(As_hi + (tr + rr) * SA + tc) =
                    make_float4(hx, hy, hz, hw);
                *reinterpret_cast<float4*>(As_lo + (tr + rr) * SA + tc) =
                    make_float4(to_tf32(v.x - hx), to_tf32(v.y - hy),
                                to_tf32(v.z - hz), to_tf32(v.w - hw));
            }
            // ---- stage B (64 x 32) hi/lo
            #pragma unroll
            for (int rr = 0; rr < CT; rr += 32) {
                const float4 v = *reinterpret_cast<const float4*>(
                    Cent + (size_t)(ct + tr + rr) * D + kt + tc);
                float hx = to_tf32(v.x), hy = to_tf32(v.y);
                float hz = to_tf32(v.z), hw = to_tf32(v.w);
                *reinterpret_cast<float4*>(Bs_hi + (tr + rr) * SA + tc) =
                    make_float4(hx, hy, hz, hw);
                *reinterpret_cast<float4*>(Bs_lo + (tr + rr) * SA + tc) =
                    make_float4(to_tf32(v.x - hx), to_tf32(v.y - hy),
                                to_tf32(v.z - hz), to_tf32(v.w - hw));
            }
            __syncthreads();

            #pragma unroll
            for (int kk = 0; kk < BK / 8; kk++) {
                const unsigned kb = (unsigned)(kk * 32);   // 8 floats = 32B
                unsigned ah[2][4], al[2][4], bh[2][4], bl[2][4];
                #pragma unroll
                for (int mt = 0; mt < 2; mt++) {
                    ldsm4(ah[mt], ah_base + aoff[mt] + kb);
                    ldsm4(al[mt], al_base + aoff[mt] + kb);
                }
                #pragma unroll
                for (int p = 0; p < 2; p++) {
                    ldsm4(bh[p], bh_base + boff[p] + kb);
                    ldsm4(bl[p], bl_base + boff[p] + kb);
                }
                #pragma unroll
                for (int mt = 0; mt < 2; mt++)
                    #pragma unroll
                    for (int p = 0; p < 2; p++)
                        #pragma unroll
                        for (int h = 0; h < 2; h++) {
                            const int nt = p * 2 + h;
                            mma_tf32(acc[mt][nt], ah[mt], bh[p][h*2], bh[p][h*2+1]);
                            mma_tf32(acc[mt][nt], al[mt], bh[p][h*2], bh[p][h*2+1]);
                            mma_tf32(acc[mt][nt], ah[mt], bl[p][h*2], bl[p][h*2+1]);
                        }
            }
            __syncthreads();
        }

        // ---- fold scores into per-thread top-2
        #pragma unroll
        for (int mt = 0; mt < 2; mt++)
            #pragma unroll
            for (int e = 0; e < 4; e++) {
                const int slot = mt * 2 + (e >> 1);
                #pragma unroll
                for (int nt = 0; nt < 4; nt++) {
                    const int cidx = ct + warp_n * 32 + nt * 8 + 2 * (lane & 3) + (e & 1);
                    const float s = fmaf(-2.f, acc[mt][nt][e], __ldg(&g_csq[cidx]));
                    if (lt(s, cidx, v1[slot], i1[slot])) {
                        v2[slot] = v1[slot]; i2[slot] = i1[slot];
                        v1[slot] = s;        i1[slot] = cidx;
                    } else if (lt(s, cidx, v2[slot], i2[slot])) {
                        v2[slot] = s; i2[slot] = cidx;
                    }
                }
            }
    }

    // ---- cross-thread top-2 reduction via smem
    const int contrib = warp_n * 4 + (lane & 3);     // 0..7
    #pragma unroll
    for (int slot = 0; slot < 4; slot++) {
        const int mt = slot >> 1, eh = slot & 1;
        const int r = warp_m * 32 + mt * 16 + eh * 8 + (lane >> 2);
        redV[r * 16 + contrib * 2 + 0] = v1[slot];
        redI[r * 16 + contrib * 2 + 0] = i1[slot];
        redV[r * 16 + contrib * 2 + 1] = v2[slot];
        redI[r * 16 + contrib * 2 + 1] = i2[slot];
    }
    __syncthreads();

    if (t < BM) {
        float bv1 = FLT_MAX, bv2 = FLT_MAX;
        int   bi1 = 0x7fffffff, bi2 = 0x7fffffff;
        #pragma unroll
        for (int e = 0; e < 16; e++) {
            const float v = redV[t * 16 + e];
            const int   i = redI[t * 16 + e];
            if (lt(v, i, bv1, bi1)) {
                bv2 = bv1; bi2 = bi1; bv1 = v; bi1 = i;
            } else if (lt(v, i, bv2, bi2)) {
                bv2 = v; bi2 = i;
            }
        }
        g_top1[row0 + t] = bi1;
        g_top2[row0 + t] = bi2;
    }
}

// one warp per token: fp64 exact pieces, then bit-replay of reference fp32 epilogue
__global__ __launch_bounds__(256)
void refine_kernel(const float* __restrict__ X,
                   const float* __restrict__ Cent,
                   float* __restrict__ out, int N, int D) {
    const int warp = (blockIdx.x * blockDim.x + threadIdx.x) >> 5;
    const int lane = threadIdx.x & 31;
    if (warp >= N) return;

    const int i1 = g_top1[warp];
    const int i2 = g_top2[warp];
    const float* x  = X + (size_t)warp * D;
    const float* cA = Cent + (size_t)i1 * D;
    const float* cB = Cent + (size_t)i2 * D;

    double x2 = 0.0, crA = 0.0, crB = 0.0;
    for (int k = lane; k < D; k += 32) {
        const double xv = (double)x[k];
        x2  = fma(xv, xv, x2);
        crA = fma(xv, (double)cA[k], crA);
        crB = fma(xv, (double)cB[k], crB);
    }
    #pragma unroll
    for (int o = 16; o > 0; o >>= 1) {
        x2  += __shfl_down_sync(0xffffffffu, x2,  o);
        crA += __shfl_down_sync(0xffffffffu, crA, o);
        crB += __shfl_down_sync(0xffffffffu, crB, o);
    }
    if (lane == 0) {
        const float x2f  = (float)x2;
        const float c2A  = (float)g_csqd[i1];
        const float c2B  = (float)g_csqd[i2];
        const float crAf = (float)crA;
        const float crBf = (float)crB;

        float sA = __fsub_rn(__fadd_rn(x2f, c2A), __fmul_rn(2.0f, crAf));
        float sB = __fsub_rn(__fadd_rn(x2f, c2B), __fmul_rn(2.0f, crBf));
        sA = fmaxf(sA, 0.f);
        sB = fmaxf(sB, 0.f);
        const float dA = __fsqrt_rn(sA);
        const float dB = __fsqrt_rn(sB);

        int win;
        if (dB < dA)      win = i2;
        else if (dA < dB) win = i1;
        else              win = (i1 < i2) ? i1 : i2;
        out[warp] = (float)win;
    }
}

extern "C" void kernel_launch(void* const* d_in, const int* in_sizes, int n_in,
                              void* d_out, int out_size) {
    const float* embed   = (const float*)d_in[0];
    const float* centers = (const float*)d_in[1];
    float* out = (float*)d_out;

    const int D = D_FIXED;
    const int N = in_sizes[0] / D;   // 32768
    const int C = in_sizes[1] / D;   // 2048

    const int smem_bytes = (2 * BM * SA + 2 * CT * SA + BM * 16 * 2) * 4;
    cudaFuncSetAttribute(rank_kernel,
                         cudaFuncAttributeMaxDynamicSharedMemorySize, smem_bytes);

    {
        const int warps_per_block = 256 / 32;
        const int nblk = (C + warps_per_block - 1) / warps_per_block;
        csq_kernel<<<nblk, 256>>>(centers, C, D);
    }
    rank_kernel<<<N / BM, NTHREADS, smem_bytes>>>(embed, centers, N, C, D);
    refine_kernel<<<(N * 32 + 255) / 256, 256>>>(embed, centers, out, N, D);
}